// round 8
// baseline (speedup 1.0000x reference)
#include <cuda_runtime.h>
#include <cstdint>

// ---------------------------------------------------------------------------
// Problem constants
// ---------------------------------------------------------------------------
#define MDIM 8192          // 4 * 2048 rows of x
#define NDIM 4096          // output features (weight rows)
#define KDIM 4096          // reduction dim
#define NX   (MDIM * KDIM) // 33,554,432
#define NW   (NDIM * KDIM) // 16,777,216

// ---------------------------------------------------------------------------
// Device scratch (static allocation — allowed; no runtime allocs anywhere)
// ---------------------------------------------------------------------------
__device__ __align__(128) int8_t g_qx[NX];
__device__ __align__(128) int8_t g_qw[NW];
__device__ unsigned int g_amax_x_bits;
__device__ unsigned int g_amax_w_bits;
__device__ float g_sx;
__device__ float g_sw;
__device__ float g_inv_denom;

// ---------------------------------------------------------------------------
// PTX helpers (sm_80-era instructions only — compile under compute_103 base)
// ---------------------------------------------------------------------------
__device__ __forceinline__ uint32_t smem_to_u32(const void* smem_ptr) {
    uint32_t addr;
    asm("{ .reg .u64 tmp; cvta.to.shared.u64 tmp, %1; cvt.u32.u64 %0, tmp; }"
        : "=r"(addr) : "l"(smem_ptr));
    return addr;
}

__device__ __forceinline__ void cp_async16(uint32_t smem_dst, const void* gmem_src) {
    asm volatile("cp.async.cg.shared.global [%0], [%1], 16;"
                 :: "r"(smem_dst),
                    "l"((unsigned long long)__cvta_generic_to_global(gmem_src))
                 : "memory");
}
__device__ __forceinline__ void cp_async_commit() {
    asm volatile("cp.async.commit_group;" ::: "memory");
}
template <int N>
__device__ __forceinline__ void cp_async_wait() {
    asm volatile("cp.async.wait_group %0;" :: "n"(N) : "memory");
}

__device__ __forceinline__ void ldsm_x4(uint32_t (&r)[4], uint32_t addr) {
    asm volatile("ldmatrix.sync.aligned.m8n8.x4.shared.b16 {%0,%1,%2,%3}, [%4];"
                 : "=r"(r[0]), "=r"(r[1]), "=r"(r[2]), "=r"(r[3]) : "r"(addr));
}

// D(s32) += A(s8, 16x32 row) * B(s8, 8x32 "col" = n-major rows of k)
__device__ __forceinline__ void mma_s8(int (&d)[4], const uint32_t (&a)[4],
                                       uint32_t b0, uint32_t b1) {
    asm volatile(
        "mma.sync.aligned.m16n8k32.row.col.s32.s8.s8.s32 "
        "{%0,%1,%2,%3}, {%4,%5,%6,%7}, {%8,%9}, {%0,%1,%2,%3};"
        : "+r"(d[0]), "+r"(d[1]), "+r"(d[2]), "+r"(d[3])
        : "r"(a[0]), "r"(a[1]), "r"(a[2]), "r"(a[3]), "r"(b0), "r"(b1));
}

// ---------------------------------------------------------------------------
// Kernel 0: reset amax accumulators
// ---------------------------------------------------------------------------
__global__ void init_kernel() {
    g_amax_x_bits = 0u;
    g_amax_w_bits = 0u;
}

// ---------------------------------------------------------------------------
// Kernel 1: amax reduction (vectorized, exact — max is associative)
// ---------------------------------------------------------------------------
__global__ void amax_kernel(const float* __restrict__ p, int n4, int sel) {
    float m = 0.0f;
    const float4* p4 = reinterpret_cast<const float4*>(p);
    for (int i = blockIdx.x * blockDim.x + threadIdx.x; i < n4;
         i += gridDim.x * blockDim.x) {
        float4 v = p4[i];
        m = fmaxf(m, fmaxf(fmaxf(fabsf(v.x), fabsf(v.y)),
                           fmaxf(fabsf(v.z), fabsf(v.w))));
    }
#pragma unroll
    for (int o = 16; o > 0; o >>= 1)
        m = fmaxf(m, __shfl_xor_sync(0xffffffffu, m, o));
    __shared__ float sm[32];
    if ((threadIdx.x & 31) == 0) sm[threadIdx.x >> 5] = m;
    __syncthreads();
    if (threadIdx.x < 32) {
        int nw = blockDim.x >> 5;
        float mm = (threadIdx.x < (unsigned)nw) ? sm[threadIdx.x] : 0.0f;
#pragma unroll
        for (int o = 16; o > 0; o >>= 1)
            mm = fmaxf(mm, __shfl_xor_sync(0xffffffffu, mm, o));
        if (threadIdx.x == 0) {
            unsigned int* dst = sel ? &g_amax_w_bits : &g_amax_x_bits;
            atomicMax(dst, __float_as_uint(mm));  // valid for non-negative floats
        }
    }
}

// ---------------------------------------------------------------------------
// Kernel 2: derive scales (fp32, exactly like reference)
// ---------------------------------------------------------------------------
__global__ void scale_kernel() {
    float ax = __uint_as_float(g_amax_x_bits);
    float aw = __uint_as_float(g_amax_w_bits);
    float sx = 127.0f / ax;
    float sw = 127.0f / aw;
    g_sx = sx;
    g_sw = sw;
    g_inv_denom = 1.0f / (sx * sw);
}

// ---------------------------------------------------------------------------
// Kernel 3: quantize to int8 (round-half-even == jnp.round), pack 4/thread
// ---------------------------------------------------------------------------
__global__ void quant_kernel(const float* __restrict__ p, int n4, int sel) {
    const float s = sel ? g_sw : g_sx;
    int8_t* q = sel ? g_qw : g_qx;
    const float4* p4 = reinterpret_cast<const float4*>(p);
    uint32_t* q4 = reinterpret_cast<uint32_t*>(q);
    for (int i = blockIdx.x * blockDim.x + threadIdx.x; i < n4;
         i += gridDim.x * blockDim.x) {
        float4 v = p4[i];
        int a0 = max(-127, min(127, __float2int_rn(v.x * s)));
        int a1 = max(-127, min(127, __float2int_rn(v.y * s)));
        int a2 = max(-127, min(127, __float2int_rn(v.z * s)));
        int a3 = max(-127, min(127, __float2int_rn(v.w * s)));
        uint32_t packed = (uint32_t)(a0 & 255) | ((uint32_t)(a1 & 255) << 8) |
                          ((uint32_t)(a2 & 255) << 16) | ((uint32_t)(a3 & 255) << 24);
        q4[i] = packed;
    }
}

// ---------------------------------------------------------------------------
// Kernel 4: int8 IMMA GEMM + dequant + bias
//   out[m][n] = (sum_k qx[m][k]*qw[n][k]) * inv + bias[n]
//
// CTA tile 256(M) x 128(N) x 64(K), 512 threads = 16 warps (4x4 warp grid),
// warp tile 64x32. 4-stage cp.async pipeline.
// SMEM rows padded to 80B: bank base = (20*row) mod 32 -> ldmatrix (8 rows x
// 16B) touches 8 disjoint 4-bank groups: conflict-free, no swizzle needed.
// ---------------------------------------------------------------------------
static constexpr int BM = 256;
static constexpr int BN = 128;
static constexpr int BK = 64;                 // bytes of K per stage
static constexpr int STAGES = 4;
static constexpr int KITERS = KDIM / BK;      // 64
static constexpr int ROW_STRIDE = 80;         // 64 data + 16 pad
static constexpr int STAGE_BYTES = (BM + BN) * ROW_STRIDE;      // 30720
static constexpr uint32_t SMEM_TOTAL = STAGES * STAGE_BYTES;    // 122880
static constexpr int A_CHUNKS = BM * (BK / 16);   // 1024
static constexpr int B_CHUNKS = BN * (BK / 16);   // 512
static constexpr int ALL_CHUNKS = A_CHUNKS + B_CHUNKS;  // 1536 (= 3 per thread)

__global__ void __launch_bounds__(512, 1)
gemm_i8_kernel(const float* __restrict__ bias, float* __restrict__ out) {
    extern __shared__ char smem[];
    const uint32_t sb = smem_to_u32(smem);
    const int tid  = threadIdx.x;
    const int lane = tid & 31;
    const int wid  = tid >> 5;
    const int wm   = wid >> 2;   // 0..3 -> 64-row slice of M
    const int wn   = wid & 3;    // 0..3 -> 32-col slice of N
    const int m0 = blockIdx.y * BM;
    const int n0 = blockIdx.x * BN;

    const int8_t* gA = g_qx + (size_t)m0 * KDIM;
    const int8_t* gB = g_qw + (size_t)n0 * KDIM;

    // ---- async load of one stage's K-tile ----
    auto load_stage = [&](int stage, int kt) {
        const uint32_t base = sb + stage * STAGE_BYTES;
        const int kbyte = kt * BK;
#pragma unroll
        for (int i = 0; i < ALL_CHUNKS / 512; i++) {
            int c = tid + i * 512;
            if (c < A_CHUNKS) {
                int r = c >> 2, ch = (c & 3) * 16;
                cp_async16(base + r * ROW_STRIDE + ch,
                           gA + (size_t)r * KDIM + kbyte + ch);
            } else {
                int c2 = c - A_CHUNKS;
                int r = c2 >> 2, ch = (c2 & 3) * 16;
                cp_async16(base + BM * ROW_STRIDE + r * ROW_STRIDE + ch,
                           gB + (size_t)r * KDIM + kbyte + ch);
            }
        }
        cp_async_commit();
    };

    // Prologue: stages 0..STAGES-2
#pragma unroll
    for (int s = 0; s < STAGES - 1; s++) load_stage(s, s);

    int d[4][4][4];   // [mt][nt][frag] accumulators (s32)
#pragma unroll
    for (int i = 0; i < 4; i++)
#pragma unroll
        for (int j = 0; j < 4; j++)
#pragma unroll
            for (int f = 0; f < 4; f++) d[i][j][f] = 0;

    // Per-lane ldmatrix source addresses (stage-relative)
    const uint32_t a_lane_off =
        (uint32_t)((lane & 15) * ROW_STRIDE + ((lane >> 4) << 4));
    const uint32_t b_lane_off =
        (uint32_t)((((lane >> 4) << 3) + (lane & 7)) * ROW_STRIDE +
                   (((lane >> 3) & 1) << 4));

    for (int kt = 0; kt < KITERS; kt++) {
        cp_async_wait<STAGES - 2>();
        __syncthreads();

        // Prefetch next stage (overwrites the stage computed last iteration;
        // safe because every warp passed the barrier above).
        if (kt + STAGES - 1 < KITERS) load_stage((kt + STAGES - 1) % STAGES, kt + STAGES - 1);
        else cp_async_commit();  // keep wait_group accounting consistent

        const uint32_t smA = sb + (kt % STAGES) * STAGE_BYTES;
        const uint32_t smB = smA + BM * ROW_STRIDE;

#pragma unroll
        for (int kc = 0; kc < 2; kc++) {          // two k=32 chunks per 64B stage
            uint32_t a[4][4];
#pragma unroll
            for (int mt = 0; mt < 4; mt++) {
                ldsm_x4(a[mt], smA + (uint32_t)((wm * 64 + mt * 16) * ROW_STRIDE +
                                                kc * 32) + a_lane_off);
            }
#pragma unroll
            for (int pr = 0; pr < 2; pr++) {      // each x4 covers two n-blocks of 8
                uint32_t b[4];
                ldsm_x4(b, smB + (uint32_t)((wn * 32 + pr * 16) * ROW_STRIDE +
                                            kc * 32) + b_lane_off);
#pragma unroll
                for (int mt = 0; mt < 4; mt++) {
                    mma_s8(d[mt][pr * 2 + 0], a[mt], b[0], b[1]);
                    mma_s8(d[mt][pr * 2 + 1], a[mt], b[2], b[3]);
                }
            }
        }
        __syncthreads();
    }

    // ---- Epilogue: dequant + bias, direct float2 stores ----
    const float inv = g_inv_denom;
    const int g   = lane >> 2;     // row within 16-row tile (0..7)
    const int tig = lane & 3;      // col pair (0..3)

    float bx[4][2];
#pragma unroll
    for (int nt = 0; nt < 4; nt++) {
        int col = n0 + wn * 32 + nt * 8 + tig * 2;
        bx[nt][0] = __ldg(bias + col);
        bx[nt][1] = __ldg(bias + col + 1);
    }

#pragma unroll
    for (int mt = 0; mt < 4; mt++) {
        int row = m0 + wm * 64 + mt * 16 + g;
#pragma unroll
        for (int nt = 0; nt < 4; nt++) {
            int col = n0 + wn * 32 + nt * 8 + tig * 2;
            float2 v0, v1;
            v0.x = (float)d[mt][nt][0] * inv + bx[nt][0];
            v0.y = (float)d[mt][nt][1] * inv + bx[nt][1];
            v1.x = (float)d[mt][nt][2] * inv + bx[nt][0];
            v1.y = (float)d[mt][nt][3] * inv + bx[nt][1];
            *reinterpret_cast<float2*>(out + (size_t)row * NDIM + col) = v0;
            *reinterpret_cast<float2*>(out + (size_t)(row + 8) * NDIM + col) = v1;
        }
    }
}

// ---------------------------------------------------------------------------
// Launch
// ---------------------------------------------------------------------------
extern "C" void kernel_launch(void* const* d_in, const int* in_sizes, int n_in,
                              void* d_out, int out_size) {
    const float* x    = (const float*)d_in[0];
    const float* w    = (const float*)d_in[1];
    const float* bias = (const float*)d_in[2];
    float* out = (float*)d_out;

    cudaFuncSetAttribute(gemm_i8_kernel,
                         cudaFuncAttributeMaxDynamicSharedMemorySize,
                         (int)SMEM_TOTAL);

    init_kernel<<<1, 1>>>();
    amax_kernel<<<2048, 256>>>(x, NX / 4, 0);
    amax_kernel<<<1024, 256>>>(w, NW / 4, 1);
    scale_kernel<<<1, 1>>>();
    quant_kernel<<<2048, 256>>>(x, NX / 4, 0);
    quant_kernel<<<1024, 256>>>(w, NW / 4, 1);

    dim3 grid(NDIM / BN, MDIM / BM);  // (32, 32)
    gemm_i8_kernel<<<grid, 512, SMEM_TOTAL>>>(bias, out);
}

// round 9
// speedup vs baseline: 1.0108x; 1.0108x over previous
#include <cuda_runtime.h>
#include <cstdint>

// ---------------------------------------------------------------------------
// Problem constants
// ---------------------------------------------------------------------------
#define MDIM 8192          // 4 * 2048 rows of x
#define NDIM 4096          // output features (weight rows)
#define KDIM 4096          // reduction dim
#define NX   (MDIM * KDIM) // 33,554,432
#define NW   (NDIM * KDIM) // 16,777,216

// ---------------------------------------------------------------------------
// Device scratch (static allocation — allowed; no runtime allocs anywhere)
// ---------------------------------------------------------------------------
__device__ __align__(128) int8_t g_qx[NX];
__device__ __align__(128) int8_t g_qw[NW];
__device__ unsigned int g_amax_x_bits;
__device__ unsigned int g_amax_w_bits;

// ---------------------------------------------------------------------------
// PTX helpers (sm_80-era instructions only — compile under compute_103 base)
// ---------------------------------------------------------------------------
__device__ __forceinline__ uint32_t smem_to_u32(const void* smem_ptr) {
    uint32_t addr;
    asm("{ .reg .u64 tmp; cvta.to.shared.u64 tmp, %1; cvt.u32.u64 %0, tmp; }"
        : "=r"(addr) : "l"(smem_ptr));
    return addr;
}

__device__ __forceinline__ void cp_async16(uint32_t smem_dst, const void* gmem_src) {
    asm volatile("cp.async.cg.shared.global [%0], [%1], 16;"
                 :: "r"(smem_dst),
                    "l"((unsigned long long)__cvta_generic_to_global(gmem_src))
                 : "memory");
}
__device__ __forceinline__ void cp_async_commit() {
    asm volatile("cp.async.commit_group;" ::: "memory");
}
template <int N>
__device__ __forceinline__ void cp_async_wait() {
    asm volatile("cp.async.wait_group %0;" :: "n"(N) : "memory");
}

__device__ __forceinline__ void ldsm_x4(uint32_t (&r)[4], uint32_t addr) {
    asm volatile("ldmatrix.sync.aligned.m8n8.x4.shared.b16 {%0,%1,%2,%3}, [%4];"
                 : "=r"(r[0]), "=r"(r[1]), "=r"(r[2]), "=r"(r[3]) : "r"(addr));
}

// D(s32) += A(s8, 16x32 row) * B(s8, 8x32 "col" = n-major rows of k)
__device__ __forceinline__ void mma_s8(int (&d)[4], const uint32_t (&a)[4],
                                       uint32_t b0, uint32_t b1) {
    asm volatile(
        "mma.sync.aligned.m16n8k32.row.col.s32.s8.s8.s32 "
        "{%0,%1,%2,%3}, {%4,%5,%6,%7}, {%8,%9}, {%0,%1,%2,%3};"
        : "+r"(d[0]), "+r"(d[1]), "+r"(d[2]), "+r"(d[3])
        : "r"(a[0]), "r"(a[1]), "r"(a[2]), "r"(a[3]), "r"(b0), "r"(b1));
}

// ---------------------------------------------------------------------------
// Kernel 0: reset amax accumulators (must run each replay — graph-safe)
// ---------------------------------------------------------------------------
__global__ void init_kernel() {
    g_amax_x_bits = 0u;
    g_amax_w_bits = 0u;
}

// ---------------------------------------------------------------------------
// Kernel 1: amax reduction (vectorized, exact — max is associative)
// ---------------------------------------------------------------------------
__global__ void amax_kernel(const float* __restrict__ p, int n4, int sel) {
    float m = 0.0f;
    const float4* p4 = reinterpret_cast<const float4*>(p);
    for (int i = blockIdx.x * blockDim.x + threadIdx.x; i < n4;
         i += gridDim.x * blockDim.x) {
        float4 v = p4[i];
        m = fmaxf(m, fmaxf(fmaxf(fabsf(v.x), fabsf(v.y)),
                           fmaxf(fabsf(v.z), fabsf(v.w))));
    }
#pragma unroll
    for (int o = 16; o > 0; o >>= 1)
        m = fmaxf(m, __shfl_xor_sync(0xffffffffu, m, o));
    __shared__ float sm[32];
    if ((threadIdx.x & 31) == 0) sm[threadIdx.x >> 5] = m;
    __syncthreads();
    if (threadIdx.x < 32) {
        int nw = blockDim.x >> 5;
        float mm = (threadIdx.x < (unsigned)nw) ? sm[threadIdx.x] : 0.0f;
#pragma unroll
        for (int o = 16; o > 0; o >>= 1)
            mm = fmaxf(mm, __shfl_xor_sync(0xffffffffu, mm, o));
        if (threadIdx.x == 0) {
            unsigned int* dst = sel ? &g_amax_w_bits : &g_amax_x_bits;
            atomicMax(dst, __float_as_uint(mm));  // valid for non-negative floats
        }
    }
}

// ---------------------------------------------------------------------------
// Kernel 2: quantize to int8 (round-half-even == jnp.round), pack 4/thread.
// Scale derived locally from amax bits (scale_kernel folded in).
// ---------------------------------------------------------------------------
__global__ void quant_kernel(const float* __restrict__ p, int n4, int sel) {
    const unsigned int abits = sel ? g_amax_w_bits : g_amax_x_bits;
    const float s = 127.0f / __uint_as_float(abits);
    int8_t* q = sel ? g_qw : g_qx;
    const float4* p4 = reinterpret_cast<const float4*>(p);
    uint32_t* q4 = reinterpret_cast<uint32_t*>(q);
    for (int i = blockIdx.x * blockDim.x + threadIdx.x; i < n4;
         i += gridDim.x * blockDim.x) {
        float4 v = p4[i];
        int a0 = max(-127, min(127, __float2int_rn(v.x * s)));
        int a1 = max(-127, min(127, __float2int_rn(v.y * s)));
        int a2 = max(-127, min(127, __float2int_rn(v.z * s)));
        int a3 = max(-127, min(127, __float2int_rn(v.w * s)));
        uint32_t packed = (uint32_t)(a0 & 255) | ((uint32_t)(a1 & 255) << 8) |
                          ((uint32_t)(a2 & 255) << 16) | ((uint32_t)(a3 & 255) << 24);
        q4[i] = packed;
    }
}

// ---------------------------------------------------------------------------
// Kernel 3: int8 IMMA GEMM + dequant + bias
//   out[m][n] = (sum_k qx[m][k]*qw[n][k]) * inv + bias[n]
//
// CTA tile 256(M) x 128(N) x 64(K), 512 threads = 16 warps (4x4 warp grid),
// warp tile 64x32. 4-stage cp.async pipeline, ONE barrier per K-iter.
// Register flow: B fragments (8 regs) loaded first, A streamed one x4 at a
// time -> live set ~90 regs, safely under the 128-reg @512thr budget
// (previous version held all A fragments live and flirted with spills).
// SMEM rows padded to 80B: bank base = (20*row) mod 32 -> every ldmatrix
// phase (8 rows x 16B) hits 8 disjoint 4-bank groups: conflict-free.
// ---------------------------------------------------------------------------
static constexpr int BM = 256;
static constexpr int BN = 128;
static constexpr int BK = 64;                 // bytes of K per stage
static constexpr int STAGES = 4;
static constexpr int KITERS = KDIM / BK;      // 64
static constexpr int ROW_STRIDE = 80;         // 64 data + 16 pad
static constexpr int STAGE_BYTES = (BM + BN) * ROW_STRIDE;      // 30720
static constexpr uint32_t SMEM_TOTAL = STAGES * STAGE_BYTES;    // 122880
static constexpr int A_CHUNKS = BM * (BK / 16);   // 1024
static constexpr int B_CHUNKS = BN * (BK / 16);   // 512
static constexpr int ALL_CHUNKS = A_CHUNKS + B_CHUNKS;  // 1536 (= 3 per thread)

__global__ void __launch_bounds__(512, 1)
gemm_i8_kernel(const float* __restrict__ bias, float* __restrict__ out) {
    extern __shared__ char smem[];
    const uint32_t sb = smem_to_u32(smem);
    const int tid  = threadIdx.x;
    const int lane = tid & 31;
    const int wid  = tid >> 5;
    const int wm   = wid >> 2;   // 0..3 -> 64-row slice of M
    const int wn   = wid & 3;    // 0..3 -> 32-col slice of N
    const int m0 = blockIdx.y * BM;
    const int n0 = blockIdx.x * BN;

    const int8_t* gA = g_qx + (size_t)m0 * KDIM;
    const int8_t* gB = g_qw + (size_t)n0 * KDIM;

    // ---- async load of one stage's K-tile ----
    auto load_stage = [&](int stage, int kt) {
        const uint32_t base = sb + stage * STAGE_BYTES;
        const int kbyte = kt * BK;
#pragma unroll
        for (int i = 0; i < ALL_CHUNKS / 512; i++) {
            int c = tid + i * 512;
            if (c < A_CHUNKS) {
                int r = c >> 2, ch = (c & 3) * 16;
                cp_async16(base + r * ROW_STRIDE + ch,
                           gA + (size_t)r * KDIM + kbyte + ch);
            } else {
                int c2 = c - A_CHUNKS;
                int r = c2 >> 2, ch = (c2 & 3) * 16;
                cp_async16(base + BM * ROW_STRIDE + r * ROW_STRIDE + ch,
                           gB + (size_t)r * KDIM + kbyte + ch);
            }
        }
        cp_async_commit();
    };

    // Prologue: stages 0..STAGES-2
#pragma unroll
    for (int s = 0; s < STAGES - 1; s++) load_stage(s, s);

    int d[4][4][4];   // [mt][nt][frag] accumulators (s32)
#pragma unroll
    for (int i = 0; i < 4; i++)
#pragma unroll
        for (int j = 0; j < 4; j++)
#pragma unroll
            for (int f = 0; f < 4; f++) d[i][j][f] = 0;

    // Per-lane ldmatrix source addresses (stage-relative)
    const uint32_t a_lane_off =
        (uint32_t)((lane & 15) * ROW_STRIDE + ((lane >> 4) << 4));
    const uint32_t b_lane_off =
        (uint32_t)((((lane >> 4) << 3) + (lane & 7)) * ROW_STRIDE +
                   (((lane >> 3) & 1) << 4));

    const uint32_t a_warp = (uint32_t)(wm * 64) * ROW_STRIDE + a_lane_off;
    const uint32_t b_warp = (uint32_t)(BM * ROW_STRIDE) +
                            (uint32_t)(wn * 32) * ROW_STRIDE + b_lane_off;

    for (int kt = 0; kt < KITERS; kt++) {
        cp_async_wait<STAGES - 2>();
        __syncthreads();   // single barrier: protects buffer (kt-1)%4 reuse

        if (kt + STAGES - 1 < KITERS) load_stage((kt + STAGES - 1) % STAGES, kt + STAGES - 1);
        else cp_async_commit();  // keep wait_group accounting consistent

        const uint32_t st = sb + (kt % STAGES) * STAGE_BYTES;

#pragma unroll
        for (int kc = 0; kc < 2; kc++) {          // two k=32 chunks per 64B stage
            // Load both B x4 fragments first (8 regs), then stream A.
            uint32_t b[2][4];
            ldsm_x4(b[0], st + b_warp + (uint32_t)(kc * 32));
            ldsm_x4(b[1], st + b_warp + (uint32_t)(16 * ROW_STRIDE + kc * 32));
#pragma unroll
            for (int mt = 0; mt < 4; mt++) {
                uint32_t a[4];
                ldsm_x4(a, st + a_warp + (uint32_t)(mt * 16 * ROW_STRIDE + kc * 32));
                mma_s8(d[mt][0], a, b[0][0], b[0][1]);
                mma_s8(d[mt][1], a, b[0][2], b[0][3]);
                mma_s8(d[mt][2], a, b[1][0], b[1][1]);
                mma_s8(d[mt][3], a, b[1][2], b[1][3]);
            }
        }
    }

    // ---- Epilogue: dequant + bias, direct float2 stores ----
    const float ax = __uint_as_float(g_amax_x_bits);
    const float aw = __uint_as_float(g_amax_w_bits);
    const float inv = 1.0f / ((127.0f / ax) * (127.0f / aw));
    const int g   = lane >> 2;     // row within 16-row tile (0..7)
    const int tig = lane & 3;      // col pair (0..3)

    float bx[4][2];
#pragma unroll
    for (int nt = 0; nt < 4; nt++) {
        int col = n0 + wn * 32 + nt * 8 + tig * 2;
        bx[nt][0] = __ldg(bias + col);
        bx[nt][1] = __ldg(bias + col + 1);
    }

#pragma unroll
    for (int mt = 0; mt < 4; mt++) {
        int row = m0 + wm * 64 + mt * 16 + g;
#pragma unroll
        for (int nt = 0; nt < 4; nt++) {
            int col = n0 + wn * 32 + nt * 8 + tig * 2;
            float2 v0, v1;
            v0.x = (float)d[mt][nt][0] * inv + bx[nt][0];
            v0.y = (float)d[mt][nt][1] * inv + bx[nt][1];
            v1.x = (float)d[mt][nt][2] * inv + bx[nt][0];
            v1.y = (float)d[mt][nt][3] * inv + bx[nt][1];
            *reinterpret_cast<float2*>(out + (size_t)row * NDIM + col) = v0;
            *reinterpret_cast<float2*>(out + (size_t)(row + 8) * NDIM + col) = v1;
        }
    }
}

// ---------------------------------------------------------------------------
// Launch (6 launches; ncu -s 5 -c 1 should land on the GEMM)
// ---------------------------------------------------------------------------
extern "C" void kernel_launch(void* const* d_in, const int* in_sizes, int n_in,
                              void* d_out, int out_size) {
    const float* x    = (const float*)d_in[0];
    const float* w    = (const float*)d_in[1];
    const float* bias = (const float*)d_in[2];
    float* out = (float*)d_out;

    cudaFuncSetAttribute(gemm_i8_kernel,
                         cudaFuncAttributeMaxDynamicSharedMemorySize,
                         (int)SMEM_TOTAL);

    init_kernel<<<1, 1>>>();
    amax_kernel<<<2048, 256>>>(x, NX / 4, 0);
    amax_kernel<<<1024, 256>>>(w, NW / 4, 1);
    quant_kernel<<<2048, 256>>>(x, NX / 4, 0);
    quant_kernel<<<1024, 256>>>(w, NW / 4, 1);

    dim3 grid(NDIM / BN, MDIM / BM);  // (32, 32)
    gemm_i8_kernel<<<grid, 512, SMEM_TOTAL>>>(bias, out);
}